// round 11
// baseline (speedup 1.0000x reference)
#include <cuda_runtime.h>
#include <cuda_fp16.h>
#include <math.h>
#include <stdint.h>

#define N_TOK 16384
#define KNN   32
#define DDIM  512
#define FEXP  8
#define EDIM  1024
#define LN_EPS 1e-5f

#define CHUNK_BYTES 16384   // one 128(rows) x 64(k) fp16 chunk, fragment-direct layout
#define NKC 16              // EDIM / 64
#define NBLK 4              // 4 col-blocks of 128 -> 512

// smem float-index layout for gemm kernel
#define ACC_W   516
#define ACC_FLOATS (64 * ACC_W)          // 33024
#define RS_OFF  ACC_FLOATS
#define RSS_OFF (ACC_FLOATS + 64)
#define ABUF_BYTE_OFF 132608             // 33152 floats * 4 (128B aligned)
#define BBUF_BYTE_OFF (ABUF_BYTE_OFF + 32768)   // A: 2 stages x 16KB
#define SMEM_TOTAL (BBUF_BYTE_OFF + 65536)      // B: 4 stages x 16KB -> 230912

// ---------------- device scratch ----------------
// A fragment-direct fp16 hi/lo: [tile(128tok)][kc(16)] chunk;
//   chunk = [mg(8)][ks(4)][lane(32)*16B]: lane 16B = a0|a1|a2|a3 (4B each)
__device__ __half g_Ah[(size_t)N_TOK * EDIM];
__device__ __half g_Al[(size_t)N_TOK * EDIM];
// B fragment-direct single fp16: [fm(16)][nb(4)][kc(16)] chunk;
//   chunk = [n8g(16)][ks(4)][lane(32)*8B]: lane 8B = b0|b1
__device__ __half g_Bf[(size_t)FEXP * 2 * DDIM * EDIM];
__device__ float g_fnw[N_TOK * FEXP];

// ---------------- helpers ----------------
__device__ __forceinline__ uint32_t smem_u32(const void* p) {
    uint32_t a;
    asm("{ .reg .u64 t; cvta.to.shared.u64 t, %1; cvt.u32.u64 %0, t; }" : "=r"(a) : "l"(p));
    return a;
}
__device__ __forceinline__ void cpa16(uint32_t s, const void* g) {
    asm volatile("cp.async.cg.shared.global [%0], [%1], 16;" :: "r"(s), "l"(g));
}
#define CP_COMMIT() asm volatile("cp.async.commit_group;" ::: "memory")
#define CP_WAIT(N)  asm volatile("cp.async.wait_group %0;" :: "n"(N) : "memory")

__device__ __forceinline__ void mma16816(float* d, const uint4& a, const uint2& b) {
    asm volatile(
        "mma.sync.aligned.m16n8k16.row.col.f32.f16.f16.f32 "
        "{%0,%1,%2,%3}, {%4,%5,%6,%7}, {%8,%9}, {%0,%1,%2,%3};"
        : "+f"(d[0]), "+f"(d[1]), "+f"(d[2]), "+f"(d[3])
        : "r"(a.x), "r"(a.y), "r"(a.z), "r"(a.w), "r"(b.x), "r"(b.y));
}
__device__ __forceinline__ float gelu_f(float x) {
    return 0.5f * x * (1.f + erff(x * 0.70710678118654752f));
}

// ---------------------------------------------------------------------------
// Kernel: weight convert  fp32 [f][e][d] -> single fp16 fragment-direct chunks
// grid = 1024 (fm*64 + nb*16 + kc), 256 threads
// ---------------------------------------------------------------------------
__global__ __launch_bounds__(256) void convert_w_kernel(
    const float* __restrict__ netW, const float* __restrict__ gateW)
{
    __shared__ float sm[64 * 129];
    const int bid = blockIdx.x;
    const int kc = bid & 15;
    const int nb = (bid >> 4) & 3;
    const int fm = bid >> 6;           // f*2 + mat
    const int f = fm >> 1, mat = fm & 1;
    const float* W = (mat ? gateW : netW) + (size_t)f * EDIM * DDIM;
    const int e0 = kc * 64, d0 = nb * 128;
    const int tid = threadIdx.x;

    #pragma unroll
    for (int i = 0; i < 32; i++) {
        int lin = tid + i * 256;
        int e = lin >> 7, d = lin & 127;
        sm[e * 129 + d] = W[(size_t)(e0 + e) * DDIM + d0 + d];
    }
    __syncthreads();

    char* dst = (char*)g_Bf + ((size_t)(fm * NBLK + nb) * NKC + kc) * CHUNK_BYTES;
    #pragma unroll
    for (int i = 0; i < 16; i++) {
        int lin = tid + i * 256;
        int j = lin & 31;        // k-pair (k = 2j, 2j+1)
        int n = lin >> 5;        // 0..127
        __half h0 = __float2half_rn(sm[(2 * j) * 129 + n]);
        __half h1 = __float2half_rn(sm[(2 * j + 1) * 129 + n]);
        int n8g = n >> 3, gr = n & 7;
        int ks = j >> 3;
        int bhalf = (j >> 2) & 1;
        int tig = j & 3;
        uint32_t off = (uint32_t)((n8g * 4 + ks) * 256 + (gr * 4 + tig) * 8 + bhalf * 4);
        __half2 ph; ph.x = h0; ph.y = h1;
        *(__half2*)(dst + off) = ph;
    }
}

// ---------------------------------------------------------------------------
// Kernel: prep — router softmax, sim softmax, argument gather, A fp16 hi/lo
// ---------------------------------------------------------------------------
__global__ __launch_bounds__(128) void prep_kernel(
    const float* __restrict__ token, const float* __restrict__ routed,
    const float* __restrict__ sim, const float* __restrict__ selW,
    const float* __restrict__ selB)
{
    __shared__ float inp[EDIM];
    __shared__ float wsm[KNN];
    __shared__ float slog[FEXP];

    const int n = blockIdx.x;
    const int tid = threadIdx.x;

    if (tid < FEXP) slog[tid] = 0.f;

    {
        float4 t4 = ((const float4*)(token + n * DDIM))[tid];
        *(float4*)(inp + tid * 4) = t4;
    }
    __syncthreads();

    float pf[FEXP];
    #pragma unroll
    for (int f = 0; f < FEXP; f++) pf[f] = 0.f;
    #pragma unroll
    for (int i = 0; i < 4; i++) {
        int d = tid + i * 128;
        float tv = inp[d];
        const float4* wp = (const float4*)(selW + d * FEXP);
        float4 w0 = wp[0], w1 = wp[1];
        pf[0] += tv * w0.x; pf[1] += tv * w0.y; pf[2] += tv * w0.z; pf[3] += tv * w0.w;
        pf[4] += tv * w1.x; pf[5] += tv * w1.y; pf[6] += tv * w1.z; pf[7] += tv * w1.w;
    }
    #pragma unroll
    for (int off = 16; off > 0; off >>= 1)
        #pragma unroll
        for (int f = 0; f < FEXP; f++)
            pf[f] += __shfl_xor_sync(0xffffffffu, pf[f], off);
    if ((tid & 31) == 0)
        #pragma unroll
        for (int f = 0; f < FEXP; f++) atomicAdd(&slog[f], pf[f]);

    if (tid < 32) {
        float s = sim[n * KNN + tid];
        float m = s;
        #pragma unroll
        for (int off = 16; off > 0; off >>= 1) m = fmaxf(m, __shfl_xor_sync(0xffffffffu, m, off));
        float e = expf(s - m);
        float su = e;
        #pragma unroll
        for (int off = 16; off > 0; off >>= 1) su += __shfl_xor_sync(0xffffffffu, su, off);
        wsm[tid] = e / su;
    }
    __syncthreads();

    if (tid == 0) {
        float lg[FEXP];
        float m = -1e30f;
        #pragma unroll
        for (int f = 0; f < FEXP; f++) { lg[f] = slog[f] + selB[f]; m = fmaxf(m, lg[f]); }
        float s = 0.f;
        #pragma unroll
        for (int f = 0; f < FEXP; f++) { lg[f] = expf(lg[f] - m); s += lg[f]; }
        float inv = 1.f / s;
        #pragma unroll
        for (int f = 0; f < FEXP; f++) g_fnw[n * FEXP + f] = lg[f] * inv;
    }

    {
        const float4* rb4 = (const float4*)(routed + (size_t)n * KNN * DDIM);
        float4 acc = make_float4(0.f, 0.f, 0.f, 0.f);
        #pragma unroll 8
        for (int k = 0; k < KNN; k++) {
            float w = wsm[k];
            float4 r = rb4[k * 128 + tid];
            acc.x += w * r.x; acc.y += w * r.y; acc.z += w * r.z; acc.w += w * r.w;
        }
        *(float4*)(inp + DDIM + tid * 4) = acc;
    }
    __syncthreads();

    // fragment-direct A scatter (fp16 hi/lo, exact split)
    const int r = n & 127;
    const int mg = r >> 4, rloc = r & 15;
    const int rhi = rloc >> 3, gr = rloc & 7;
    char* bah = (char*)g_Ah + (size_t)(n >> 7) * (NKC * CHUNK_BYTES);
    char* bal = (char*)g_Al + (size_t)(n >> 7) * (NKC * CHUNK_BYTES);
    #pragma unroll
    for (int i = 0; i < 4; i++) {
        int p = tid + i * 128;      // pair 0..511
        int e = 2 * p;
        int kc = e >> 6;
        int k = e & 63;
        int ks = k >> 4;
        int kk = k & 15;
        int khalf = kk >> 3;
        int tig = (kk >> 1) & 3;
        float v0 = inp[e], v1 = inp[e + 1];
        __half h0 = __float2half_rn(v0);
        __half h1 = __float2half_rn(v1);
        __half l0 = __float2half_rn(v0 - __half2float(h0));
        __half l1 = __float2half_rn(v1 - __half2float(h1));
        uint32_t off = (uint32_t)kc * CHUNK_BYTES +
                       (uint32_t)((mg * 4 + ks) * 512 + (gr * 4 + tig) * 16 +
                                  (khalf * 2 + rhi) * 4);
        __half2 ph; ph.x = h0; ph.y = h1;
        __half2 pl; pl.x = l0; pl.y = l1;
        *(__half2*)(bah + off) = ph;
        *(__half2*)(bal + off) = pl;
    }
}

// ---------------------------------------------------------------------------
// Kernel: fused grouped GEMM (f-loop) + epilogue + combine in smem.
// grid (mat=2, mt=256), 256 threads. CTA: 64 tokens x 512 cols, all 8 f.
// net (mat=0): 2-term fp16 (exact A). gate (mat=1): 1-term fp16.
// Pair-chunk pipeline: one wait_group(0) + barrier per 2 chunks.
// ---------------------------------------------------------------------------
__global__ __launch_bounds__(256, 1) void gemm_kernel(
    const float* __restrict__ netB, const float* __restrict__ lng,
    const float* __restrict__ lnb, const float* __restrict__ gateB,
    float* __restrict__ outP, float* __restrict__ outG)
{
    extern __shared__ float smemf[];
    char* scp = (char*)smemf;
    const uint32_t sbase = smem_u32(smemf);
    const int tid = threadIdx.x;
    const int lane = tid & 31, wid = tid >> 5;
    const int mw = wid >> 2, nw = wid & 3;    // 2 x 4 warp grid
    const int g = lane >> 2, tig = lane & 3;
    const int mat = blockIdx.x, mt = blockIdx.y;
    const int tile = mt >> 1;
    const uint32_t rowhalf = (uint32_t)(mt & 1) * 8192;   // 64-row half of A chunk
    const int n0 = mt * 64;
    const int RB = mw * 32, CB = nw * 32;

    float* accum = smemf;
    float* rsum = smemf + RS_OFF;
    float* rssq = smemf + RSS_OFF;

    for (int i = tid; i < ACC_FLOATS + 128; i += 256) smemf[i] = 0.f;
    __syncthreads();

    const char* Ahg = (const char*)g_Ah + (size_t)tile * (NKC * CHUNK_BYTES);
    const char* Alg = (const char*)g_Al + (size_t)tile * (NKC * CHUNK_BYTES);

    auto prefetch = [&](int j) {           // j in [0, 512)
        int klin = j >> 2, nb = j & 3;
        int fj = klin >> 4, kc = klin & 15;
        size_t boff = ((size_t)((fj * 2 + mat) * NBLK + nb) * NKC + kc) * CHUNK_BYTES;
        const char* bp = (const char*)g_Bf + boff;
        uint32_t dst = sbase + BBUF_BYTE_OFF + (uint32_t)(j & 3) * 16384;
        #pragma unroll
        for (int i = 0; i < 4; i++) {
            uint32_t o = (uint32_t)tid * 16 + i * 4096;
            cpa16(dst + o, bp + o);
        }
        if (nb == 0) {
            const char* ah = Ahg + (size_t)kc * CHUNK_BYTES + rowhalf;
            uint32_t adst = sbase + ABUF_BYTE_OFF + (uint32_t)(klin & 1) * 16384;
            #pragma unroll
            for (int i = 0; i < 2; i++) {
                uint32_t o = (uint32_t)tid * 16 + i * 4096;
                cpa16(adst + o, ah + o);
            }
            if (mat == 0) {
                const char* al = Alg + (size_t)kc * CHUNK_BYTES + rowhalf;
                #pragma unroll
                for (int i = 0; i < 2; i++) {
                    uint32_t o = (uint32_t)tid * 16 + i * 4096;
                    cpa16(adst + 8192 + o, al + o);
                }
            }
        }
        CP_COMMIT();
    };

    prefetch(0);
    prefetch(1);

    const float invD = 1.f / (float)DDIM;
    const uint32_t laneA = (uint32_t)lane * 16;
    const uint32_t laneB = (uint32_t)lane * 8;

    for (int f = 0; f < FEXP; f++) {
        float acc[4][2][4][4];
        #pragma unroll
        for (int a = 0; a < 4; a++)
            #pragma unroll
            for (int b = 0; b < 2; b++)
                #pragma unroll
                for (int c = 0; c < 4; c++)
                    #pragma unroll
                    for (int d = 0; d < 4; d++) acc[a][b][c][d] = 0.f;

        for (int kc = 0; kc < NKC; kc++) {
            const int klin = f * NKC + kc;
            const char* Ab = scp + ABUF_BYTE_OFF + (size_t)(klin & 1) * 16384;
            uint4 AH[4][2], AL[4][2];     // [ks][m16] — live across the 4 nb chunks
            #pragma unroll
            for (int nbp = 0; nbp < 2; nbp++) {       // pairs: chunks (jb, jb+1)
                const int jb = klin * 4 + nbp * 2;
                CP_WAIT(0);
                __syncthreads();
                prefetch((jb + 2) & 511);
                prefetch((jb + 3) & 511);
                if (nbp == 0) {
                    #pragma unroll
                    for (int ks = 0; ks < 4; ks++) {
                        AH[ks][0] = *(const uint4*)(Ab + ((mw * 2 + 0) * 4 + ks) * 512 + laneA);
                        AH[ks][1] = *(const uint4*)(Ab + ((mw * 2 + 1) * 4 + ks) * 512 + laneA);
                        if (mat == 0) {
                            AL[ks][0] = *(const uint4*)(Ab + 8192 + ((mw * 2 + 0) * 4 + ks) * 512 + laneA);
                            AL[ks][1] = *(const uint4*)(Ab + 8192 + ((mw * 2 + 1) * 4 + ks) * 512 + laneA);
                        }
                    }
                }
                #pragma unroll
                for (int half = 0; half < 2; half++) {
                    const int nb = nbp * 2 + half;
                    const char* Bb = scp + BBUF_BYTE_OFF + (size_t)((jb + half) & 3) * 16384;
                    #pragma unroll
                    for (int ks = 0; ks < 4; ks++) {
                        #pragma unroll
                        for (int n8 = 0; n8 < 4; n8++) {
                            uint32_t bo = ((nw * 4 + n8) * 4 + ks) * 256 + laneB;
                            uint2 bf = *(const uint2*)(Bb + bo);
                            mma16816(acc[nb][0][n8], AH[ks][0], bf);
                            mma16816(acc[nb][1][n8], AH[ks][1], bf);
                            if (mat == 0) {
                                mma16816(acc[nb][0][n8], AL[ks][0], bf);
                                mma16816(acc[nb][1][n8], AL[ks][1], bf);
                            }
                        }
                    }
                }
            }
        }

        // -------- epilogue for expert f --------
        if (mat == 0 && tid < 64) { rsum[tid] = 0.f; rssq[tid] = 0.f; }
        __syncthreads();

        if (mat == 0) {
            float rs[4] = {0.f, 0.f, 0.f, 0.f}, rq[4] = {0.f, 0.f, 0.f, 0.f};
            #pragma unroll
            for (int nb = 0; nb < 4; nb++)
                #pragma unroll
                for (int n8 = 0; n8 < 4; n8++) {
                    int colb = nb * 128 + CB + n8 * 8 + 2 * tig;
                    float2 b2 = __ldg((const float2*)(netB + f * DDIM + colb));
                    #pragma unroll
                    for (int m16 = 0; m16 < 2; m16++)
                        #pragma unroll
                        for (int h = 0; h < 2; h++) {
                            float v0 = gelu_f(acc[nb][m16][n8][2 * h] + b2.x);
                            float v1 = gelu_f(acc[nb][m16][n8][2 * h + 1] + b2.y);
                            acc[nb][m16][n8][2 * h] = v0;
                            acc[nb][m16][n8][2 * h + 1] = v1;
                            int idx = m16 * 2 + h;
                            rs[idx] += v0 + v1;
                            rq[idx] += v0 * v0 + v1 * v1;
                        }
                }
            #pragma unroll
            for (int m16 = 0; m16 < 2; m16++)
                #pragma unroll
                for (int h = 0; h < 2; h++) {
                    int row = RB + m16 * 16 + g + 8 * h;
                    atomicAdd(&rsum[row], rs[m16 * 2 + h]);
                    atomicAdd(&rssq[row], rq[m16 * 2 + h]);
                }
        }
        __syncthreads();

        if (mat == 0) {
            #pragma unroll
            for (int m16 = 0; m16 < 2; m16++)
                #pragma unroll
                for (int h = 0; h < 2; h++) {
                    int row = RB + m16 * 16 + g + 8 * h;
                    float mu = rsum[row] * invD;
                    float var = rssq[row] * invD - mu * mu;
                    float rstd = rsqrtf(var + LN_EPS);
                    float wf = __ldg(&g_fnw[(n0 + row) * FEXP + f]);
                    #pragma unroll
                    for (int nb = 0; nb < 4; nb++)
                        #pragma unroll
                        for (int n8 = 0; n8 < 4; n8++) {
                            int colb = nb * 128 + CB + n8 * 8 + 2 * tig;
                            float2 g2 = __ldg((const float2*)(lng + f * DDIM + colb));
                            float2 e2 = __ldg((const float2*)(lnb + f * DDIM + colb));
                            float p0 = (acc[nb][m16][n8][2 * h] - mu) * rstd * g2.x + e2.x;
                            float p1 = (acc[nb][m16][n8][2 * h + 1] - mu) * rstd * g2.y + e2.y;
                            float2* cell = (float2*)(accum + row * ACC_W + colb);
                            float2 cv = *cell;
                            cv.x += wf * p0; cv.y += wf * p1;
                            *cell = cv;
                        }
                }
        } else {
            #pragma unroll
            for (int m16 = 0; m16 < 2; m16++)
                #pragma unroll
                for (int h = 0; h < 2; h++) {
                    int row = RB + m16 * 16 + g + 8 * h;
                    float wf = __ldg(&g_fnw[(n0 + row) * FEXP + f]);
                    #pragma unroll
                    for (int nb = 0; nb < 4; nb++)
                        #pragma unroll
                        for (int n8 = 0; n8 < 4; n8++) {
                            int colb = nb * 128 + CB + n8 * 8 + 2 * tig;
                            float2 b2 = __ldg((const float2*)(gateB + f * DDIM + colb));
                            float s0 = 1.f / (1.f + __expf(-(acc[nb][m16][n8][2 * h] + b2.x)));
                            float s1 = 1.f / (1.f + __expf(-(acc[nb][m16][n8][2 * h + 1] + b2.y)));
                            float2* cell = (float2*)(accum + row * ACC_W + colb);
                            float2 cv = *cell;
                            cv.x += wf * s0; cv.y += wf * s1;
                            *cell = cv;
                        }
                }
        }
        __syncthreads();
    }

    CP_WAIT(0);
    __syncthreads();

    float* outbase = mat ? outG : outP;
    #pragma unroll
    for (int i = 0; i < 32; i++) {
        int idx4 = tid + i * 256;            // 8192 float4s
        int row = idx4 >> 7, c4 = idx4 & 127;
        float4 v = *(const float4*)(accum + row * ACC_W + c4 * 4);
        *(float4*)(outbase + (size_t)(n0 + row) * DDIM + c4 * 4) = v;
    }
}

// ---------------------------------------------------------------------------
extern "C" void kernel_launch(void* const* d_in, const int* in_sizes, int n_in,
                              void* d_out, int out_size) {
    const float* token  = (const float*)d_in[0];
    const float* routed = (const float*)d_in[1];
    const float* sim    = (const float*)d_in[2];
    const float* selW   = (const float*)d_in[3];
    const float* selB   = (const float*)d_in[4];
    const float* netW   = (const float*)d_in[5];
    const float* netB   = (const float*)d_in[6];
    const float* lng    = (const float*)d_in[7];
    const float* lnb    = (const float*)d_in[8];
    const float* gateW  = (const float*)d_in[9];
    const float* gateB  = (const float*)d_in[10];

    float* outP = (float*)d_out;
    float* outG = (float*)d_out + (size_t)N_TOK * DDIM;

    cudaFuncSetAttribute(gemm_kernel, cudaFuncAttributeMaxDynamicSharedMemorySize,
                         SMEM_TOTAL);

    convert_w_kernel<<<FEXP * 2 * NBLK * NKC, 256>>>(netW, gateW);
    prep_kernel<<<N_TOK, 128>>>(token, routed, sim, selW, selB);
    dim3 grid(2, N_TOK / 64);            // mat-major: interleaves net/gate tiles
    gemm_kernel<<<grid, 256, SMEM_TOTAL>>>(netB, lng, lnb, gateB, outP, outG);
}

// round 12
// speedup vs baseline: 1.0396x; 1.0396x over previous
#include <cuda_runtime.h>
#include <cuda_fp16.h>
#include <math.h>
#include <stdint.h>

#define N_TOK 16384
#define KNN   32
#define DDIM  512
#define FEXP  8
#define EDIM  1024
#define LN_EPS 1e-5f

#define CHUNK_BYTES 16384   // one 128(rows) x 64(k) fp16 chunk, fragment-direct layout
#define NKC 16              // EDIM / 64
#define NBLK 4              // 4 col-blocks of 128 -> 512

// smem float-index layout for gemm kernel
#define ACC_W   516
#define ACC_FLOATS (64 * ACC_W)          // 33024
#define RS_OFF  ACC_FLOATS
#define RSS_OFF (ACC_FLOATS + 64)
#define ABUF_BYTE_OFF 132608             // 33152 floats * 4 (128B aligned)
#define BBUF_BYTE_OFF (ABUF_BYTE_OFF + 32768)   // A: 2 stages x 16KB
#define SMEM_TOTAL (BBUF_BYTE_OFF + 65536)      // B: 4 stages x 16KB -> 230912

// ---------------- device scratch ----------------
__device__ __half g_Ah[(size_t)N_TOK * EDIM];
__device__ __half g_Al[(size_t)N_TOK * EDIM];
__device__ __half g_Bf[(size_t)FEXP * 2 * DDIM * EDIM];
__device__ float g_fnw[N_TOK * FEXP];

// ---------------- helpers ----------------
__device__ __forceinline__ uint32_t smem_u32(const void* p) {
    uint32_t a;
    asm("{ .reg .u64 t; cvta.to.shared.u64 t, %1; cvt.u32.u64 %0, t; }" : "=r"(a) : "l"(p));
    return a;
}
__device__ __forceinline__ void cpa16(uint32_t s, const void* g) {
    asm volatile("cp.async.cg.shared.global [%0], [%1], 16;" :: "r"(s), "l"(g));
}
#define CP_COMMIT() asm volatile("cp.async.commit_group;" ::: "memory")
#define CP_WAIT(N)  asm volatile("cp.async.wait_group %0;" :: "n"(N) : "memory")

__device__ __forceinline__ void mma16816(float* d, const uint4& a, const uint2& b) {
    asm volatile(
        "mma.sync.aligned.m16n8k16.row.col.f32.f16.f16.f32 "
        "{%0,%1,%2,%3}, {%4,%5,%6,%7}, {%8,%9}, {%0,%1,%2,%3};"
        : "+f"(d[0]), "+f"(d[1]), "+f"(d[2]), "+f"(d[3])
        : "r"(a.x), "r"(a.y), "r"(a.z), "r"(a.w), "r"(b.x), "r"(b.y));
}
__device__ __forceinline__ float gelu_f(float x) {
    return 0.5f * x * (1.f + erff(x * 0.70710678118654752f));
}

// ---------------------------------------------------------------------------
// Kernel: weight convert  fp32 [f][e][d] -> single fp16 fragment-direct chunks
// grid = 1024 (fm*64 + nb*16 + kc), 256 threads
// ---------------------------------------------------------------------------
__global__ __launch_bounds__(256) void convert_w_kernel(
    const float* __restrict__ netW, const float* __restrict__ gateW)
{
    __shared__ float sm[64 * 129];
    const int bid = blockIdx.x;
    const int kc = bid & 15;
    const int nb = (bid >> 4) & 3;
    const int fm = bid >> 6;           // f*2 + mat
    const int f = fm >> 1, mat = fm & 1;
    const float* W = (mat ? gateW : netW) + (size_t)f * EDIM * DDIM;
    const int e0 = kc * 64, d0 = nb * 128;
    const int tid = threadIdx.x;

    #pragma unroll
    for (int i = 0; i < 32; i++) {
        int lin = tid + i * 256;
        int e = lin >> 7, d = lin & 127;
        sm[e * 129 + d] = W[(size_t)(e0 + e) * DDIM + d0 + d];
    }
    __syncthreads();

    char* dst = (char*)g_Bf + ((size_t)(fm * NBLK + nb) * NKC + kc) * CHUNK_BYTES;
    #pragma unroll
    for (int i = 0; i < 16; i++) {
        int lin = tid + i * 256;
        int j = lin & 31;        // k-pair (k = 2j, 2j+1)
        int n = lin >> 5;        // 0..127
        __half h0 = __float2half_rn(sm[(2 * j) * 129 + n]);
        __half h1 = __float2half_rn(sm[(2 * j + 1) * 129 + n]);
        int n8g = n >> 3, gr = n & 7;
        int ks = j >> 3;
        int bhalf = (j >> 2) & 1;
        int tig = j & 3;
        uint32_t off = (uint32_t)((n8g * 4 + ks) * 256 + (gr * 4 + tig) * 8 + bhalf * 4);
        __half2 ph; ph.x = h0; ph.y = h1;
        *(__half2*)(dst + off) = ph;
    }
}

// ---------------------------------------------------------------------------
// Kernel: prep — router softmax, sim softmax, argument gather, A fp16 hi/lo
// ---------------------------------------------------------------------------
__global__ __launch_bounds__(128) void prep_kernel(
    const float* __restrict__ token, const float* __restrict__ routed,
    const float* __restrict__ sim, const float* __restrict__ selW,
    const float* __restrict__ selB)
{
    __shared__ float inp[EDIM];
    __shared__ float wsm[KNN];
    __shared__ float slog[FEXP];

    const int n = blockIdx.x;
    const int tid = threadIdx.x;

    if (tid < FEXP) slog[tid] = 0.f;

    {
        float4 t4 = ((const float4*)(token + n * DDIM))[tid];
        *(float4*)(inp + tid * 4) = t4;
    }
    __syncthreads();

    float pf[FEXP];
    #pragma unroll
    for (int f = 0; f < FEXP; f++) pf[f] = 0.f;
    #pragma unroll
    for (int i = 0; i < 4; i++) {
        int d = tid + i * 128;
        float tv = inp[d];
        const float4* wp = (const float4*)(selW + d * FEXP);
        float4 w0 = wp[0], w1 = wp[1];
        pf[0] += tv * w0.x; pf[1] += tv * w0.y; pf[2] += tv * w0.z; pf[3] += tv * w0.w;
        pf[4] += tv * w1.x; pf[5] += tv * w1.y; pf[6] += tv * w1.z; pf[7] += tv * w1.w;
    }
    #pragma unroll
    for (int off = 16; off > 0; off >>= 1)
        #pragma unroll
        for (int f = 0; f < FEXP; f++)
            pf[f] += __shfl_xor_sync(0xffffffffu, pf[f], off);
    if ((tid & 31) == 0)
        #pragma unroll
        for (int f = 0; f < FEXP; f++) atomicAdd(&slog[f], pf[f]);

    if (tid < 32) {
        float s = sim[n * KNN + tid];
        float m = s;
        #pragma unroll
        for (int off = 16; off > 0; off >>= 1) m = fmaxf(m, __shfl_xor_sync(0xffffffffu, m, off));
        float e = expf(s - m);
        float su = e;
        #pragma unroll
        for (int off = 16; off > 0; off >>= 1) su += __shfl_xor_sync(0xffffffffu, su, off);
        wsm[tid] = e / su;
    }
    __syncthreads();

    if (tid == 0) {
        float lg[FEXP];
        float m = -1e30f;
        #pragma unroll
        for (int f = 0; f < FEXP; f++) { lg[f] = slog[f] + selB[f]; m = fmaxf(m, lg[f]); }
        float s = 0.f;
        #pragma unroll
        for (int f = 0; f < FEXP; f++) { lg[f] = expf(lg[f] - m); s += lg[f]; }
        float inv = 1.f / s;
        #pragma unroll
        for (int f = 0; f < FEXP; f++) g_fnw[n * FEXP + f] = lg[f] * inv;
    }

    {
        const float4* rb4 = (const float4*)(routed + (size_t)n * KNN * DDIM);
        float4 acc = make_float4(0.f, 0.f, 0.f, 0.f);
        #pragma unroll 8
        for (int k = 0; k < KNN; k++) {
            float w = wsm[k];
            float4 r = rb4[k * 128 + tid];
            acc.x += w * r.x; acc.y += w * r.y; acc.z += w * r.z; acc.w += w * r.w;
        }
        *(float4*)(inp + DDIM + tid * 4) = acc;
    }
    __syncthreads();

    // fragment-direct A scatter (fp16 hi/lo, exact split)
    const int r = n & 127;
    const int mg = r >> 4, rloc = r & 15;
    const int rhi = rloc >> 3, gr = rloc & 7;
    char* bah = (char*)g_Ah + (size_t)(n >> 7) * (NKC * CHUNK_BYTES);
    char* bal = (char*)g_Al + (size_t)(n >> 7) * (NKC * CHUNK_BYTES);
    #pragma unroll
    for (int i = 0; i < 4; i++) {
        int p = tid + i * 128;      // pair 0..511
        int e = 2 * p;
        int kc = e >> 6;
        int k = e & 63;
        int ks = k >> 4;
        int kk = k & 15;
        int khalf = kk >> 3;
        int tig = (kk >> 1) & 3;
        float v0 = inp[e], v1 = inp[e + 1];
        __half h0 = __float2half_rn(v0);
        __half h1 = __float2half_rn(v1);
        __half l0 = __float2half_rn(v0 - __half2float(h0));
        __half l1 = __float2half_rn(v1 - __half2float(h1));
        uint32_t off = (uint32_t)kc * CHUNK_BYTES +
                       (uint32_t)((mg * 4 + ks) * 512 + (gr * 4 + tig) * 16 +
                                  (khalf * 2 + rhi) * 4);
        __half2 ph; ph.x = h0; ph.y = h1;
        __half2 pl; pl.x = l0; pl.y = l1;
        *(__half2*)(bah + off) = ph;
        *(__half2*)(bal + off) = pl;
    }
}

// ---------------------------------------------------------------------------
// Kernel: fused grouped GEMM (f-loop) + epilogue + combine in smem.
// grid (mat=2, mt=256) interleaved, 256 threads. CTA: 64 tok x 512 cols, 8 f.
// net (mat=0): 2-term fp16 (exact A). gate (mat=1): 1-term fp16.
// R9 pipeline: 4-stage B, CP_WAIT(2), one barrier per chunk, prefetch dist 3.
// ---------------------------------------------------------------------------
__global__ __launch_bounds__(256, 1) void gemm_kernel(
    const float* __restrict__ netB, const float* __restrict__ lng,
    const float* __restrict__ lnb, const float* __restrict__ gateB,
    float* __restrict__ outP, float* __restrict__ outG)
{
    extern __shared__ float smemf[];
    char* scp = (char*)smemf;
    const uint32_t sbase = smem_u32(smemf);
    const int tid = threadIdx.x;
    const int lane = tid & 31, wid = tid >> 5;
    const int mw = wid >> 2, nw = wid & 3;    // 2 x 4 warp grid
    const int g = lane >> 2, tig = lane & 3;
    const int mat = blockIdx.x, mt = blockIdx.y;
    const int tile = mt >> 1;
    const uint32_t rowhalf = (uint32_t)(mt & 1) * 8192;   // 64-row half of A chunk
    const int n0 = mt * 64;
    const int RB = mw * 32, CB = nw * 32;

    float* accum = smemf;
    float* rsum = smemf + RS_OFF;
    float* rssq = smemf + RSS_OFF;

    for (int i = tid; i < ACC_FLOATS + 128; i += 256) smemf[i] = 0.f;
    __syncthreads();

    const char* Ahg = (const char*)g_Ah + (size_t)tile * (NKC * CHUNK_BYTES);
    const char* Alg = (const char*)g_Al + (size_t)tile * (NKC * CHUNK_BYTES);

    auto prefetch = [&](int j) {           // j in [0, 512)
        int klin = j >> 2, nb = j & 3;
        int fj = klin >> 4, kc = klin & 15;
        size_t boff = ((size_t)((fj * 2 + mat) * NBLK + nb) * NKC + kc) * CHUNK_BYTES;
        const char* bp = (const char*)g_Bf + boff;
        uint32_t dst = sbase + BBUF_BYTE_OFF + (uint32_t)(j & 3) * 16384;
        #pragma unroll
        for (int i = 0; i < 4; i++) {
            uint32_t o = (uint32_t)tid * 16 + i * 4096;
            cpa16(dst + o, bp + o);
        }
        if (nb == 0) {
            const char* ah = Ahg + (size_t)kc * CHUNK_BYTES + rowhalf;
            uint32_t adst = sbase + ABUF_BYTE_OFF + (uint32_t)(klin & 1) * 16384;
            #pragma unroll
            for (int i = 0; i < 2; i++) {
                uint32_t o = (uint32_t)tid * 16 + i * 4096;
                cpa16(adst + o, ah + o);
            }
            if (mat == 0) {
                const char* al = Alg + (size_t)kc * CHUNK_BYTES + rowhalf;
                #pragma unroll
                for (int i = 0; i < 2; i++) {
                    uint32_t o = (uint32_t)tid * 16 + i * 4096;
                    cpa16(adst + 8192 + o, al + o);
                }
            }
        }
        CP_COMMIT();
    };

    prefetch(0);
    prefetch(1);
    prefetch(2);

    const float invD = 1.f / (float)DDIM;
    const uint32_t laneA = (uint32_t)lane * 16;
    const uint32_t laneB = (uint32_t)lane * 8;

    for (int f = 0; f < FEXP; f++) {
        float acc[4][2][4][4];
        #pragma unroll
        for (int a = 0; a < 4; a++)
            #pragma unroll
            for (int b = 0; b < 2; b++)
                #pragma unroll
                for (int c = 0; c < 4; c++)
                    #pragma unroll
                    for (int d = 0; d < 4; d++) acc[a][b][c][d] = 0.f;

        for (int kc = 0; kc < NKC; kc++) {
            const int klin = f * NKC + kc;
            const char* Ab = scp + ABUF_BYTE_OFF + (size_t)(klin & 1) * 16384;
            uint4 AH[4][2], AL[4][2];     // [ks][m16] — live across nb iterations
            #pragma unroll
            for (int nb = 0; nb < 4; nb++) {
                const int j = klin * 4 + nb;
                const char* Bb = scp + BBUF_BYTE_OFF + (size_t)(j & 3) * 16384;
                CP_WAIT(2);
                __syncthreads();
                if (nb == 0) {
                    #pragma unroll
                    for (int ks = 0; ks < 4; ks++) {
                        AH[ks][0] = *(const uint4*)(Ab + ((mw * 2 + 0) * 4 + ks) * 512 + laneA);
                        AH[ks][1] = *(const uint4*)(Ab + ((mw * 2 + 1) * 4 + ks) * 512 + laneA);
                        if (mat == 0) {
                            AL[ks][0] = *(const uint4*)(Ab + 8192 + ((mw * 2 + 0) * 4 + ks) * 512 + laneA);
                            AL[ks][1] = *(const uint4*)(Ab + 8192 + ((mw * 2 + 1) * 4 + ks) * 512 + laneA);
                        }
                    }
                }
                #pragma unroll
                for (int ks = 0; ks < 4; ks++) {
                    #pragma unroll
                    for (int n8 = 0; n8 < 4; n8++) {
                        uint32_t bo = ((nw * 4 + n8) * 4 + ks) * 256 + laneB;
                        uint2 bf = *(const uint2*)(Bb + bo);
                        mma16816(acc[nb][0][n8], AH[ks][0], bf);
                        mma16816(acc[nb][1][n8], AH[ks][1], bf);
                        if (mat == 0) {
                            mma16816(acc[nb][0][n8], AL[ks][0], bf);
                            mma16816(acc[nb][1][n8], AL[ks][1], bf);
                        }
                    }
                }
                prefetch((j + 3) & 511);
            }
        }

        // -------- epilogue for expert f --------
        if (mat == 0 && tid < 64) { rsum[tid] = 0.f; rssq[tid] = 0.f; }
        __syncthreads();

        if (mat == 0) {
            float rs[4] = {0.f, 0.f, 0.f, 0.f}, rq[4] = {0.f, 0.f, 0.f, 0.f};
            #pragma unroll
            for (int nb = 0; nb < 4; nb++)
                #pragma unroll
                for (int n8 = 0; n8 < 4; n8++) {
                    int colb = nb * 128 + CB + n8 * 8 + 2 * tig;
                    float2 b2 = __ldg((const float2*)(netB + f * DDIM + colb));
                    #pragma unroll
                    for (int m16 = 0; m16 < 2; m16++)
                        #pragma unroll
                        for (int h = 0; h < 2; h++) {
                            float v0 = gelu_f(acc[nb][m16][n8][2 * h] + b2.x);
                            float v1 = gelu_f(acc[nb][m16][n8][2 * h + 1] + b2.y);
                            acc[nb][m16][n8][2 * h] = v0;
                            acc[nb][m16][n8][2 * h + 1] = v1;
                            int idx = m16 * 2 + h;
                            rs[idx] += v0 + v1;
                            rq[idx] += v0 * v0 + v1 * v1;
                        }
                }
            #pragma unroll
            for (int m16 = 0; m16 < 2; m16++)
                #pragma unroll
                for (int h = 0; h < 2; h++) {
                    int row = RB + m16 * 16 + g + 8 * h;
                    atomicAdd(&rsum[row], rs[m16 * 2 + h]);
                    atomicAdd(&rssq[row], rq[m16 * 2 + h]);
                }
        }
        __syncthreads();

        if (mat == 0) {
            #pragma unroll
            for (int m16 = 0; m16 < 2; m16++)
                #pragma unroll
                for (int h = 0; h < 2; h++) {
                    int row = RB + m16 * 16 + g + 8 * h;
                    float mu = rsum[row] * invD;
                    float var = rssq[row] * invD - mu * mu;
                    float rstd = rsqrtf(var + LN_EPS);
                    float wf = __ldg(&g_fnw[(n0 + row) * FEXP + f]);
                    #pragma unroll
                    for (int nb = 0; nb < 4; nb++)
                        #pragma unroll
                        for (int n8 = 0; n8 < 4; n8++) {
                            int colb = nb * 128 + CB + n8 * 8 + 2 * tig;
                            float2 g2 = __ldg((const float2*)(lng + f * DDIM + colb));
                            float2 e2 = __ldg((const float2*)(lnb + f * DDIM + colb));
                            float p0 = (acc[nb][m16][n8][2 * h] - mu) * rstd * g2.x + e2.x;
                            float p1 = (acc[nb][m16][n8][2 * h + 1] - mu) * rstd * g2.y + e2.y;
                            float2* cell = (float2*)(accum + row * ACC_W + colb);
                            float2 cv = *cell;
                            cv.x += wf * p0; cv.y += wf * p1;
                            *cell = cv;
                        }
                }
        } else {
            #pragma unroll
            for (int m16 = 0; m16 < 2; m16++)
                #pragma unroll
                for (int h = 0; h < 2; h++) {
                    int row = RB + m16 * 16 + g + 8 * h;
                    float wf = __ldg(&g_fnw[(n0 + row) * FEXP + f]);
                    #pragma unroll
                    for (int nb = 0; nb < 4; nb++)
                        #pragma unroll
                        for (int n8 = 0; n8 < 4; n8++) {
                            int colb = nb * 128 + CB + n8 * 8 + 2 * tig;
                            float2 b2 = __ldg((const float2*)(gateB + f * DDIM + colb));
                            float s0 = 1.f / (1.f + __expf(-(acc[nb][m16][n8][2 * h] + b2.x)));
                            float s1 = 1.f / (1.f + __expf(-(acc[nb][m16][n8][2 * h + 1] + b2.y)));
                            float2* cell = (float2*)(accum + row * ACC_W + colb);
                            float2 cv = *cell;
                            cv.x += wf * s0; cv.y += wf * s1;
                            *cell = cv;
                        }
                }
        }
        __syncthreads();
    }

    CP_WAIT(0);
    __syncthreads();

    float* outbase = mat ? outG : outP;
    #pragma unroll
    for (int i = 0; i < 32; i++) {
        int idx4 = tid + i * 256;            // 8192 float4s
        int row = idx4 >> 7, c4 = idx4 & 127;
        float4 v = *(const float4*)(accum + row * ACC_W + c4 * 4);
        *(float4*)(outbase + (size_t)(n0 + row) * DDIM + c4 * 4) = v;
    }
}

// ---------------------------------------------------------------------------
extern "C" void kernel_launch(void* const* d_in, const int* in_sizes, int n_in,
                              void* d_out, int out_size) {
    const float* token  = (const float*)d_in[0];
    const float* routed = (const float*)d_in[1];
    const float* sim    = (const float*)d_in[2];
    const float* selW   = (const float*)d_in[3];
    const float* selB   = (const float*)d_in[4];
    const float* netW   = (const float*)d_in[5];
    const float* netB   = (const float*)d_in[6];
    const float* lng    = (const float*)d_in[7];
    const float* lnb    = (const float*)d_in[8];
    const float* gateW  = (const float*)d_in[9];
    const float* gateB  = (const float*)d_in[10];

    float* outP = (float*)d_out;
    float* outG = (float*)d_out + (size_t)N_TOK * DDIM;

    cudaFuncSetAttribute(gemm_kernel, cudaFuncAttributeMaxDynamicSharedMemorySize,
                         SMEM_TOTAL);

    convert_w_kernel<<<FEXP * 2 * NBLK * NKC, 256>>>(netW, gateW);
    prep_kernel<<<N_TOK, 128>>>(token, routed, sim, selW, selB);
    dim3 grid(2, N_TOK / 64);            // mat-major: interleaves net/gate tiles
    gemm_kernel<<<grid, 256, SMEM_TOTAL>>>(netB, lng, lnb, gateB, outP, outG);
}